// round 15
// baseline (speedup 1.0000x reference)
#include <cuda_runtime.h>
#include <cstdint>

#define BB 32
#define CC 512
#define HWP 784
#define MM 200
#define NCC 50
#define NMM 4
#define KK 5

#define MT 32
#define PT 16            // pixels per tile (8 pairs)
#define CT 8             // channels per pipeline step
#define SPT 64           // steps per tile (CC / CT)
#define NTILE (7 * 49)   // 343 (m,p) tiles
#define TOTW (NTILE * SPT)          // 21952 step-units
#define NCTA 304                    // 152 SMs x 2 resident CTAs
#define BASEW (TOTW / NCTA)         // 72
#define REMW (TOTW - BASEW * NCTA) // 64 CTAs get one extra step

// smem layout (float2 units), per-channel layout identical to validated R10:
// per channel per operand: 4 groups of 8 rows, group stride 72 f2
// (8 rows x 8 f2 + 8 f2 pad); within each row the four 16B chunks are
// XOR-swizzled by (row&3). Two pipeline buffers (double buffer).
#define CHF2 288                   // 4 * 72
#define STAGEF2 (CT * CHF2)        // 2304 per operand
#define BUFF2 (2 * STAGEF2)        // x + m = 4608
#define ARENAF2 (2 * BUFF2)        // 9216 f2 = 73728 B

typedef unsigned long long ull;

__device__ float g_bg[BB * KK * HWP];
__device__ float g_pm[BB * MM * KK];
// per-tile accumulators (red.add targets): [tile][b(32)][m(32)][pc(8)] float2
__device__ float2 g_acc[NTILE * 8192];          // 22.5 MB
// per-tile denominators: [tile][m(32)][pc(8)] float2
__device__ float2 g_aden[NTILE * 256];          // 0.7 MB

__device__ __forceinline__ unsigned su32(const void* p) {
    return (unsigned)__cvta_generic_to_shared(p);
}

__device__ __forceinline__ void red2(float2* p, ull v) {
    const float2 f = *(const float2*)&v;
    asm volatile("red.global.add.v2.f32 [%0], {%1, %2};"
                 :: "l"(p), "f"(f.x), "f"(f.y) : "memory");
}

// ---------------------------------------------------------------------------
// bg (+ fused clutter normalization + zeroing of g_pm / g_acc / g_aden)
// ---------------------------------------------------------------------------
__global__ void __launch_bounds__(256) bg_kernel(const float* __restrict__ x,
                                                 const float* __restrict__ clutter) {
    __shared__ float cls[KK * CC];
    __shared__ float part[16][16 * KK];
    __shared__ float red[8];
    __shared__ float rtot;

    const int tid = threadIdx.x;
    const int b = blockIdx.y;
    const int px0 = blockIdx.x * 16;
    const int lane = tid & 31, w = tid >> 5;

    // zero scratch (401408 threads total)
    const int gid = (blockIdx.y * 49 + blockIdx.x) * 256 + tid;
    if (gid < BB * MM * KK) g_pm[gid] = 0.0f;
    const float2 z2 = make_float2(0.f, 0.f);
    for (int i = gid; i < NTILE * 8192; i += 49 * BB * 256) g_acc[i] = z2;
    if (gid < NTILE * 256) g_aden[gid] = z2;

    for (int k = 0; k < KK; ++k) {
        float v0 = fminf(fmaxf(clutter[k * CC + tid], 0.f), 1.f);
        float v1 = fminf(fmaxf(clutter[k * CC + 256 + tid], 0.f), 1.f);
        float s = v0 + v1;
        #pragma unroll
        for (int o = 16; o > 0; o >>= 1) s += __shfl_xor_sync(0xffffffffu, s, o);
        if (lane == 0) red[w] = s;
        __syncthreads();
        if (tid == 0) {
            float r = 0.f;
            #pragma unroll
            for (int q = 0; q < 8; ++q) r += red[q];
            rtot = fmaxf(r, 1e-12f);
        }
        __syncthreads();
        const float inv = __frcp_rn(rtot);
        cls[k * CC + tid] = v0 * inv;
        cls[k * CC + 256 + tid] = v1 * inv;
        __syncthreads();
    }

    const int px = tid & 15;
    const int cg = tid >> 4;
    float a0 = 0.f, a1 = 0.f, a2 = 0.f, a3 = 0.f, a4 = 0.f;
    const float* xb = x + ((size_t)b * CC + cg * 32) * HWP + px0 + px;
    #pragma unroll 4
    for (int ci = 0; ci < 32; ++ci) {
        const int c = cg * 32 + ci;
        const float xv = xb[(size_t)ci * HWP];
        a0 += xv * cls[0 * CC + c];
        a1 += xv * cls[1 * CC + c];
        a2 += xv * cls[2 * CC + c];
        a3 += xv * cls[3 * CC + c];
        a4 += xv * cls[4 * CC + c];
    }
    part[cg][px * KK + 0] = a0;
    part[cg][px * KK + 1] = a1;
    part[cg][px * KK + 2] = a2;
    part[cg][px * KK + 3] = a3;
    part[cg][px * KK + 4] = a4;
    __syncthreads();

    if (tid < 16 * KK) {
        float s = 0.f;
        #pragma unroll
        for (int g = 0; g < 16; ++g) s += part[g][tid];
        const int p = tid / KK, k = tid % KK;
        g_bg[((size_t)b * KK + k) * HWP + px0 + p] = __logf(s * 0.3f + 1e-10f);
    }
}

// ---------------------------------------------------------------------------
// fg: 304 persistent-style CTAs, each owns a contiguous 72-73 step range of
// the flattened (tile, step) work list -> perfectly balanced, <=3 fragments.
// Mainloop per fragment identical to the validated R10/R13 core.
// Partials land in g_acc / g_aden via red.global.add.v2.f32.
// ---------------------------------------------------------------------------
__global__ void __launch_bounds__(128, 2) fg_kernel(const float* __restrict__ x,
                                                    const float* __restrict__ mix) {
    extern __shared__ float2 arena[];

    const int tid = threadIdx.x;
    const int cta = blockIdx.x;
    int pos = cta * BASEW + (cta < REMW ? cta : REMW);
    const int end = pos + BASEW + (cta < REMW ? 1 : 0);

    // ---- tile-independent mappings
    const int c_l = tid >> 5;
    const int r   = tid & 31;
    const int rowb_f2 = c_l * CHF2 + 72 * (r >> 3) + 8 * (r & 7);
    const int rsw = r & 3;
    const unsigned sm_b = su32(arena);

    const int pc = tid & 7;
    const int mg = (tid >> 3) & 3;
    const int bg = tid >> 5;
    int pcx[4];
    #pragma unroll
    for (int t = 0; t < 4; ++t) pcx[t] = 2 * ((pc >> 1) ^ t) + (pc & 1);
    const int xob = bg * 72;
    const int mob = mg * 72;
    const int dof = mob + 8 * bg + pcx[bg & 3];

#define LOAD_STAGE(buf, s)                                                        \
    {                                                                             \
        const size_t go = (size_t)(s) * CT * HWP;                                 \
        _Pragma("unroll")                                                         \
        for (int ch = 0; ch < 2; ++ch) {                                          \
            _Pragma("unroll")                                                     \
            for (int q = 0; q < 4; ++q) {                                         \
                const int df2 = rowb_f2 + ch * (4 * CHF2) + 2 * (q ^ rsw);        \
                unsigned dx = sm_b + (unsigned)(((buf) * BUFF2 + df2) * 8);       \
                unsigned dm = dx + (unsigned)(STAGEF2 * 8);                       \
                asm volatile("cp.async.cg.shared.global [%0], [%1], 16;"          \
                             ::"r"(dx), "l"(xsrc + go + ch * 4 * HWP + 4 * q));   \
                asm volatile("cp.async.cg.shared.global [%0], [%1], 16;"          \
                             ::"r"(dm), "l"(msrc + go + ch * 4 * HWP + 4 * q));   \
            }                                                                     \
        }                                                                         \
        asm volatile("cp.async.commit_group;");                                   \
    }

    while (pos < end) {
        const int tile = pos >> 6;               // /SPT (64)
        const int s0   = pos & (SPT - 1);
        const int rem  = end - pos;
        const int avail = SPT - s0;
        const int nst  = (rem < avail) ? rem : avail;

        const int mtile = tile / 49;
        const int ptile = tile - mtile * 49;
        const int mbase = mtile * MT;
        const int px0   = ptile * PT;
        const int mrow  = (mbase + r < MM) ? mbase + r : MM - 1;
        const float* xsrc = x   + ((size_t)r    * CC + c_l) * HWP + px0;
        const float* msrc = mix + ((size_t)mrow * CC + c_l) * HWP + px0;

        ull acc[8][8];
        ull dden[2] = {0ull, 0ull};
        #pragma unroll
        for (int i = 0; i < 8; ++i)
            #pragma unroll
            for (int j = 0; j < 8; ++j) acc[i][j] = 0ull;

        // prologue: step s0 -> buffer 0
        LOAD_STAGE(0, s0)

        for (int t = 0; t < nst; ++t) {
            const int cur = t & 1;
            const int nxt = cur ^ 1;
            const int lds = s0 + ((t + 1 < nst) ? t + 1 : t);

            asm volatile("cp.async.wait_group 0;");
            __syncthreads();
            LOAD_STAGE(nxt, lds)

            const ull* xb = (const ull*)(arena + cur * BUFF2);
            const ull* mb = xb + STAGEF2;
            #pragma unroll
            for (int c = 0; c < CT; ++c) {
                ull xr[8];
                #pragma unroll
                for (int i = 0; i < 8; ++i)
                    xr[i] = xb[c * CHF2 + xob + 8 * i + pcx[i & 3]];
                const ull d0 = mb[c * CHF2 + dof];
                const ull d1 = mb[c * CHF2 + dof + 32];
                asm("add.rn.f32x2 %0, %0, %1;" : "+l"(dden[0]) : "l"(d0));
                asm("add.rn.f32x2 %0, %0, %1;" : "+l"(dden[1]) : "l"(d1));
                #pragma unroll
                for (int j = 0; j < 8; ++j) {
                    const ull mr = mb[c * CHF2 + mob + 8 * j + pcx[j & 3]];
                    #pragma unroll
                    for (int i = 0; i < 8; ++i)
                        asm("fma.rn.f32x2 %0, %1, %2, %0;"
                            : "+l"(acc[i][j]) : "l"(xr[i]), "l"(mr));
                }
            }
        }

        // fragment epilogue: atomic partial dump (disjoint-in-time, <=2 per addr)
        float2* aout = g_acc + (size_t)tile * 8192;
        #pragma unroll
        for (int j = 0; j < 8; ++j)
            #pragma unroll
            for (int i = 0; i < 8; ++i)
                red2(&aout[((bg * 8 + i) * 32 + (mg * 8 + j)) * 8 + pc],
                     acc[i][j]);
        red2(&g_aden[tile * 256 + (mg * 8 + bg) * 8 + pc], dden[0]);
        red2(&g_aden[tile * 256 + (mg * 8 + bg + 4) * 8 + pc], dden[1]);

        pos += nst;
    }
#undef LOAD_STAGE
}

// ---------------------------------------------------------------------------
// combine: normalize + log + occlusion-max + g_pm atomics. grid 343, block 256.
// ---------------------------------------------------------------------------
__global__ void __launch_bounds__(256) combine_kernel() {
    __shared__ float2 sden[256];

    const int tid   = threadIdx.x;
    const int tile  = blockIdx.x;
    const int mtile = tile / 49;
    const int ptile = tile - mtile * 49;
    const int mbase = mtile * MT;
    const int px0   = ptile * PT;

    const float2* pa = g_acc + (size_t)tile * 8192;
    sden[tid] = g_aden[tile * 256 + tid];
    __syncthreads();

    #pragma unroll
    for (int rep = 0; rep < 4; ++rep) {
        const int cell = tid + rep * 256;      // 0..1023 = b*32 + ml
        const int b = cell >> 5;
        const int ml = cell & 31;
        const int m_g = mbase + ml;
        float2 fv[8];
        #pragma unroll
        for (int p = 0; p < 8; ++p) {
            const float2 u = pa[cell * 8 + p];
            const float2 d = sden[ml * 8 + p];
            const float ivx = __fdividef(0.7f, fmaxf(d.x, 1e-12f));
            const float ivy = __fdividef(0.7f, fmaxf(d.y, 1e-12f));
            fv[p].x = __logf(u.x * ivx + 1e-10f);
            fv[p].y = __logf(u.y * ivy + 1e-10f);
        }
        float sk[KK];
        #pragma unroll
        for (int k = 0; k < KK; ++k) {
            float s = 0.f;
            const float* bgp = g_bg + ((size_t)b * KK + k) * HWP + px0;
            #pragma unroll
            for (int pp = 0; pp < 4; ++pp) {
                const float4 bv = *(const float4*)(bgp + pp * 4);
                s += fmaxf(fv[2 * pp].x, bv.x) + fmaxf(fv[2 * pp].y, bv.y) +
                     fmaxf(fv[2 * pp + 1].x, bv.z) + fmaxf(fv[2 * pp + 1].y, bv.w);
            }
            sk[k] = s;
        }
        if (m_g < MM) {
            float* pmp = g_pm + ((size_t)b * MM + m_g) * KK;
            #pragma unroll
            for (int k = 0; k < KK; ++k) atomicAdd(&pmp[k], sk[k]);
        }
    }
}

// ---------------------------------------------------------------------------
__global__ void final_kernel(float* __restrict__ out) {
    const int idx = blockIdx.x * 256 + threadIdx.x;
    if (idx >= BB * NCC) return;
    const int b = idx / NCC, nc = idx % NCC;
    const float* p = g_pm + ((size_t)b * MM + nc * NMM) * KK;
    float m = -3.402823466e+38f;
    #pragma unroll
    for (int t = 0; t < NMM * KK; ++t) m = fmaxf(m, p[t]);
    out[idx] = m;
}

// ---------------------------------------------------------------------------
extern "C" void kernel_launch(void* const* d_in, const int* in_sizes, int n_in,
                              void* d_out, int out_size) {
    const float* x       = (const float*)d_in[0];
    const float* mix     = (const float*)d_in[1];
    const float* clutter = (const float*)d_in[2];
    float* out = (float*)d_out;

    const int fg_smem = ARENAF2 * 8;     // 73728 B, 2 CTAs/SM
    cudaFuncSetAttribute(fg_kernel, cudaFuncAttributeMaxDynamicSharedMemorySize,
                         fg_smem);

    bg_kernel<<<dim3(49, BB), 256>>>(x, clutter);
    fg_kernel<<<NCTA, 128, fg_smem>>>(x, mix);
    combine_kernel<<<NTILE, 256>>>();
    final_kernel<<<(BB * NCC + 255) / 256, 256>>>(out);
}